// round 2
// baseline (speedup 1.0000x reference)
#include <cuda_runtime.h>
#include <math.h>

#define BATCH 8192
#define DIM   256
#define TM    128
#define TN    128
#define BK    16
#define COLB  (BATCH / TN)   // 64 column blocks

// Scratch (static device arrays — no allocation allowed)
__device__ float g_rowc[BATCH];               // log(n_miss_i) - log(1-q_i)
__device__ float g_colc[BATCH];               // log(q_j)
__device__ float g_pos[BATCH];                // diagonal similarities
__device__ float g_partial[COLB * BATCH];     // per-colblock partial row sums (2 MB)
__device__ float g_terms[BATCH];              // per-row loss terms

// ---------------------------------------------------------------------------
// Kernel 1: per-row stats: n_miss, rowc, colc, pos_sim (one block per row)
// ---------------------------------------------------------------------------
__global__ void k_rowstats(const float* __restrict__ X, const float* __restrict__ Y,
                           const long long* __restrict__ ids, const float* __restrict__ q) {
    __shared__ int   s_cnt[256];
    __shared__ float s_pos[256];
    const int i = blockIdx.x;
    const int t = threadIdx.x;
    const long long myid = ids[i];

    int cnt = 0;
    #pragma unroll 4
    for (int j = t; j < BATCH; j += 256) cnt += (ids[j] == myid) ? 1 : 0;

    // diagonal dot product: DIM == 256 == blockDim.x, one element per thread
    float p = X[(size_t)i * DIM + t] * Y[(size_t)i * DIM + t];

    s_cnt[t] = cnt;
    s_pos[t] = p;
    __syncthreads();
    for (int s = 128; s > 0; s >>= 1) {
        if (t < s) { s_cnt[t] += s_cnt[t + s]; s_pos[t] += s_pos[t + s]; }
        __syncthreads();
    }
    if (t == 0) {
        const int n_miss = BATCH - s_cnt[0];   // self is counted in s_cnt
        const float qi = q[i];
        g_rowc[i] = logf((float)n_miss) - logf(1.0f - qi);
        g_colc[i] = logf(qi);
        g_pos[i]  = s_pos[0];
    }
}

// ---------------------------------------------------------------------------
// Kernel 2: fused GEMM + masked-exp epilogue.
// 128x128 tile per CTA, 256 threads, 8x8 micro-tile per thread, BK=16.
// Writes deterministic partial row sums into g_partial[colBlock][row].
// ---------------------------------------------------------------------------
__global__ __launch_bounds__(256, 2)
void k_main(const float* __restrict__ X, const float* __restrict__ Y,
            const long long* __restrict__ ids) {
    __shared__ float As[BK][TM];
    __shared__ float Bs[BK][TN];
    __shared__ float part[TM][17];   // padded to kill bank conflicts

    const int rowBase = blockIdx.y * TM;
    const int colBase = blockIdx.x * TN;
    const int tid = threadIdx.x;
    const int tx = tid & 15;         // 0..15 -> column group
    const int ty = tid >> 4;         // 0..15 -> row group

    float acc[8][8];
    #pragma unroll
    for (int i = 0; i < 8; i++)
        #pragma unroll
        for (int j = 0; j < 8; j++) acc[i][j] = 0.0f;

    for (int k0 = 0; k0 < DIM; k0 += BK) {
        // Load 128x16 tiles of X and Y (each 512 float4s; 2 per thread per matrix)
        #pragma unroll
        for (int l = 0; l < 2; l++) {
            const int idx = tid + l * 256;
            const int r   = idx >> 2;           // 0..127
            const int kq  = (idx & 3) << 2;     // 0,4,8,12
            float4 va = *(const float4*)(X + (size_t)(rowBase + r) * DIM + k0 + kq);
            As[kq + 0][r] = va.x; As[kq + 1][r] = va.y;
            As[kq + 2][r] = va.z; As[kq + 3][r] = va.w;
            float4 vb = *(const float4*)(Y + (size_t)(colBase + r) * DIM + k0 + kq);
            Bs[kq + 0][r] = vb.x; Bs[kq + 1][r] = vb.y;
            Bs[kq + 2][r] = vb.z; Bs[kq + 3][r] = vb.w;
        }
        __syncthreads();

        #pragma unroll
        for (int kk = 0; kk < BK; kk++) {
            float a[8], b[8];
            *(float4*)(a)     = *(const float4*)&As[kk][ty * 8];
            *(float4*)(a + 4) = *(const float4*)&As[kk][ty * 8 + 4];
            *(float4*)(b)     = *(const float4*)&Bs[kk][tx * 8];
            *(float4*)(b + 4) = *(const float4*)&Bs[kk][tx * 8 + 4];
            #pragma unroll
            for (int i = 0; i < 8; i++)
                #pragma unroll
                for (int j = 0; j < 8; j++)
                    acc[i][j] = fmaf(a[i], b[j], acc[i][j]);
        }
        __syncthreads();
    }

    // ---- Epilogue: masked exp(sim - rowc_i - logq_j), partial row sums ----
    long long idc[8];
    float lq[8];
    #pragma unroll
    for (int j = 0; j < 8; j++) {
        const int c = colBase + tx * 8 + j;
        idc[j] = ids[c];
        lq[j]  = g_colc[c];
    }
    #pragma unroll
    for (int i = 0; i < 8; i++) {
        const int r = rowBase + ty * 8 + i;
        const long long idr = ids[r];
        const float rc = g_rowc[r];
        float s = 0.0f;
        #pragma unroll
        for (int j = 0; j < 8; j++) {
            if (idc[j] != idr)
                s += __expf(acc[i][j] - rc - lq[j]);
        }
        part[ty * 8 + i][tx] = s;
    }
    __syncthreads();

    if (tid < TM) {
        float s = 0.0f;
        #pragma unroll
        for (int t = 0; t < 16; t++) s += part[tid][t];
        g_partial[(size_t)blockIdx.x * BATCH + rowBase + tid] = s;
    }
}

// ---------------------------------------------------------------------------
// Kernel 3: per-row loss term (deterministic reduction over col blocks)
// ---------------------------------------------------------------------------
__global__ void k_rowloss() {
    const int r = blockIdx.x * 256 + threadIdx.x;
    float s = 0.0f;
    #pragma unroll 8
    for (int c = 0; c < COLB; c++) s += g_partial[(size_t)c * BATCH + r];
    const float p = g_pos[r];
    g_terms[r] = -p + logf(expf(p) + s);
}

// ---------------------------------------------------------------------------
// Kernel 4: mean over rows
// ---------------------------------------------------------------------------
__global__ void k_final(float* __restrict__ out) {
    __shared__ float sm[1024];
    const int t = threadIdx.x;
    float s = 0.0f;
    for (int r = t; r < BATCH; r += 1024) s += g_terms[r];
    sm[t] = s;
    __syncthreads();
    for (int st = 512; st > 0; st >>= 1) {
        if (t < st) sm[t] += sm[t + st];
        __syncthreads();
    }
    if (t == 0) out[0] = sm[0] / (float)BATCH;
}

// ---------------------------------------------------------------------------
extern "C" void kernel_launch(void* const* d_in, const int* in_sizes, int n_in,
                              void* d_out, int out_size) {
    const float*     X   = (const float*)d_in[0];      // input_emb  [B, D] f32
    const float*     Y   = (const float*)d_in[1];      // target_emb [B, D] f32
    const long long* ids = (const long long*)d_in[2];  // target_ids [B, 1] i64
    const float*     q   = (const float*)d_in[3];      // q_probas   [B]    f32

    k_rowstats<<<BATCH, 256>>>(X, Y, ids, q);
    dim3 grid(COLB, BATCH / TM);
    k_main<<<grid, 256>>>(X, Y, ids);
    k_rowloss<<<BATCH / 256, 256>>>();
    k_final<<<1, 1024>>>((float*)d_out);
}

// round 7
// speedup vs baseline: 1.3331x; 1.3331x over previous
#include <cuda_runtime.h>
#include <cuda_bf16.h>
#include <mma.h>
#include <cstdint>
#include <math.h>

using namespace nvcuda;

#define BATCH 8192
#define DIM   256
#define TM    128
#define TN    128
#define KCHUNK 32
#define NCHUNK (DIM / KCHUNK)     // 8
#define COLB  (BATCH / TN)        // 64
#define LDE   40                  // tile leading dim (elements): 80B rows, conflict-free LDSM
#define TILE_ELEMS (128 * LDE)    // 5120 bf16 = 10240 B per tile

// ---------------- static device scratch ------------------------------------
__device__ float g_rowc[BATCH];
__device__ float g_colc[BATCH];
__device__ float g_pos[BATCH];
__device__ float g_partial[COLB * BATCH];
__device__ float g_terms[BATCH];
__device__ __align__(16) __nv_bfloat16 g_Xh[BATCH * DIM];
__device__ __align__(16) __nv_bfloat16 g_Xl[BATCH * DIM];
__device__ __align__(16) __nv_bfloat16 g_Yh[BATCH * DIM];
__device__ __align__(16) __nv_bfloat16 g_Yl[BATCH * DIM];

// ---------------------------------------------------------------------------
// Kernel 0: split fp32 -> bf16 hi/lo pairs (no pointer punning)
// ---------------------------------------------------------------------------
__global__ void k_split(const float* __restrict__ X, const float* __restrict__ Y) {
    const int n = BATCH * DIM;
    int t = blockIdx.x * blockDim.x + threadIdx.x;   // one bf16x2 pair per thread
    if (t >= n) return;                               // t indexes pairs over BOTH halves? no:
    // handle X and Y with same thread (two loads) to keep grid simple
    {
        const float2 v = reinterpret_cast<const float2*>(X)[t >> 1 == t >> 1 ? t : t]; // placeholder
    }
}

// (real split below; the above dummy removed by rewrite)
__global__ void k_split2(const float* __restrict__ src, __nv_bfloat16* __restrict__ dh,
                         __nv_bfloat16* __restrict__ dl) {
    int t = blockIdx.x * blockDim.x + threadIdx.x;   // pair index
    const int np = BATCH * DIM / 2;
    if (t >= np) return;
    const float2 v = reinterpret_cast<const float2*>(src)[t];
    const float hx = __bfloat162float(__float2bfloat16(v.x));
    const float hy = __bfloat162float(__float2bfloat16(v.y));
    __nv_bfloat162 h = __floats2bfloat162_rn(v.x, v.y);          // hi parts (rn per lane)
    // recompute hi consistently with h
    const float h0 = __bfloat162float(__low2bfloat16(h));
    const float h1 = __bfloat162float(__high2bfloat16(h));
    __nv_bfloat162 l = __floats2bfloat162_rn(v.x - h0, v.y - h1);
    reinterpret_cast<__nv_bfloat162*>(dh)[t] = h;
    reinterpret_cast<__nv_bfloat162*>(dl)[t] = l;
    (void)hx; (void)hy;
}

// ---------------------------------------------------------------------------
// Kernel 1: per-row stats (identical structure to the R2-passing version)
// ---------------------------------------------------------------------------
__global__ void k_rowstats(const float* __restrict__ X, const float* __restrict__ Y,
                           const long long* __restrict__ ids, const float* __restrict__ q) {
    __shared__ int   s_cnt[256];
    __shared__ float s_pos[256];
    const int i = blockIdx.x;
    const int t = threadIdx.x;
    const long long myid = ids[i];
    int cnt = 0;
    #pragma unroll 4
    for (int j = t; j < BATCH; j += 256) cnt += (ids[j] == myid) ? 1 : 0;
    float p = X[(size_t)i * DIM + t] * Y[(size_t)i * DIM + t];
    s_cnt[t] = cnt; s_pos[t] = p;
    __syncthreads();
    for (int s = 128; s > 0; s >>= 1) {
        if (t < s) { s_cnt[t] += s_cnt[t + s]; s_pos[t] += s_pos[t + s]; }
        __syncthreads();
    }
    if (t == 0) {
        const int n_miss = BATCH - s_cnt[0];
        const float qi = q[i];
        g_rowc[i] = logf((float)n_miss) - logf(1.0f - qi);
        g_colc[i] = logf(qi);
        g_pos[i]  = s_pos[0];
    }
}

// ---------------------------------------------------------------------------
// Main: WMMA split-bf16 GEMM (hi*hi + hi*lo + lo*hi) + fused masked-exp.
// 128x128 CTA tile, 8 warps (4x2), warp tile 32x64. KCHUNK=32, ld=40.
// All shared memory static (45KB). LDG register prefetch, no cp.async/asm.
// ---------------------------------------------------------------------------
__global__ __launch_bounds__(256, 1)
void k_main(const long long* __restrict__ ids) {
    __shared__ __align__(128) __nv_bfloat16 tiles[4 * TILE_ELEMS];   // 40960 B
    __shared__ float     s_rc[128];
    __shared__ float     s_cq[128];
    __shared__ long long s_rid[128];
    __shared__ long long s_cid[128];
    __shared__ float     part[256];

    __nv_bfloat16* sAh = tiles;
    __nv_bfloat16* sAl = tiles + TILE_ELEMS;
    __nv_bfloat16* sBh = tiles + 2 * TILE_ELEMS;
    __nv_bfloat16* sBl = tiles + 3 * TILE_ELEMS;

    const int tid  = threadIdx.x;
    const int wid  = tid >> 5;
    const int lane = tid & 31;
    const int wm   = wid >> 1;          // 0..3 : 32-row band
    const int wn   = wid & 1;           // 0..1 : 64-col band
    const int rowBase = blockIdx.y * TM;
    const int colBase = blockIdx.x * TN;

    if (tid < 128) {
        s_rc[tid]  = g_rowc[rowBase + tid];
        s_cq[tid]  = g_colc[colBase + tid];
        s_rid[tid] = ids[rowBase + tid];
        s_cid[tid] = ids[colBase + tid];
    }

    wmma::fragment<wmma::accumulator, 16, 16, 16, float> acc[2][4];
    #pragma unroll
    for (int i = 0; i < 2; i++)
        #pragma unroll
        for (int j = 0; j < 4; j++) wmma::fill_fragment(acc[i][j], 0.0f);

    // prefetch/store bookkeeping: 2048 uint4 per chunk / 256 threads = 8 each
    // per tile m: 512 uint4 -> this thread handles 2 of them
    const int r0 = tid >> 1;                 // 0..127  (two threads per row)
    const int sgA = (tid & 1) * 2;           // segs {0,1} or {2,3}
    uint4 pf[8];

    auto ldg_chunk = [&](int chunk) {
        const __nv_bfloat16* srcs[4] = {g_Xh, g_Xl, g_Yh, g_Yl};
        #pragma unroll
        for (int m = 0; m < 4; m++) {
            const int gbase = (m < 2) ? rowBase : colBase;
            const __nv_bfloat16* p =
                srcs[m] + (size_t)(gbase + r0) * DIM + chunk * KCHUNK + sgA * 8;
            pf[m * 2 + 0] = *reinterpret_cast<const uint4*>(p);
            pf[m * 2 + 1] = *reinterpret_cast<const uint4*>(p + 8);
        }
    };
    auto sts_chunk = [&]() {
        #pragma unroll
        for (int m = 0; m < 4; m++) {
            __nv_bfloat16* dst = tiles + m * TILE_ELEMS + r0 * LDE + sgA * 8;
            *reinterpret_cast<uint4*>(dst)     = pf[m * 2 + 0];
            *reinterpret_cast<uint4*>(dst + 8) = pf[m * 2 + 1];
        }
    };

    ldg_chunk(0);
    sts_chunk();
    __syncthreads();

    for (int c = 0; c < NCHUNK; c++) {
        if (c + 1 < NCHUNK) ldg_chunk(c + 1);

        #pragma unroll
        for (int ks = 0; ks < 2; ks++) {
            wmma::fragment<wmma::matrix_a, 16, 16, 16, __nv_bfloat16, wmma::row_major> aH[2], aL[2];
            #pragma unroll
            for (int i = 0; i < 2; i++) {
                const int ro = (wm * 32 + i * 16) * LDE + ks * 16;
                wmma::load_matrix_sync(aH[i], sAh + ro, LDE);
                wmma::load_matrix_sync(aL[i], sAl + ro, LDE);
            }
            #pragma unroll
            for (int j = 0; j < 4; j++) {
                wmma::fragment<wmma::matrix_b, 16, 16, 16, __nv_bfloat16, wmma::col_major> bH, bL;
                const int co = (wn * 64 + j * 16) * LDE + ks * 16;
                wmma::load_matrix_sync(bH, sBh + co, LDE);
                wmma::load_matrix_sync(bL, sBl + co, LDE);
                #pragma unroll
                for (int i = 0; i < 2; i++) {
                    wmma::mma_sync(acc[i][j], aH[i], bH, acc[i][j]);
                    wmma::mma_sync(acc[i][j], aH[i], bL, acc[i][j]);
                    wmma::mma_sync(acc[i][j], aL[i], bH, acc[i][j]);
                }
            }
        }
        __syncthreads();
        if (c + 1 < NCHUNK) {
            sts_chunk();
            __syncthreads();
        }
    }

    // ---- epilogue: spill acc -> slab (reuses tiles), masked exp, row sums ----
    float* slab = reinterpret_cast<float*>(tiles) + wid * 1024;   // 4KB per warp
    const int lrow = wm * 32 + lane;             // this lane's CTA row
    const long long idr = s_rid[lrow];
    const float rc = s_rc[lrow];
    float rowsum = 0.0f;

    #pragma unroll
    for (int h = 0; h < 2; h++) {                // two 32-col halves
        #pragma unroll
        for (int i = 0; i < 2; i++)
            #pragma unroll
            for (int j = 0; j < 2; j++)
                wmma::store_matrix_sync(slab + (i * 16) * 32 + j * 16,
                                        acc[i][h * 2 + j], 32, wmma::mem_row_major);
        __syncwarp();
        const float4* rowp = reinterpret_cast<const float4*>(slab + lane * 32);
        #pragma unroll
        for (int c4 = 0; c4 < 8; c4++) {
            const int cc = (c4 + lane) & 7;      // xor-rotate: conflict-free
            const float4 v = rowp[cc];
            const int cb = wn * 64 + h * 32 + cc * 4;
            const float vv[4] = {v.x, v.y, v.z, v.w};
            #pragma unroll
            for (int e = 0; e < 4; e++) {
                const int col = cb + e;
                if (s_cid[col] != idr)
                    rowsum += __expf(vv[e] - rc - s_cq[col]);
            }
        }
        __syncwarp();
    }
    part[lrow * 2 + wn] = rowsum;
    __syncthreads();
    if (tid < 128)
        g_partial[(size_t)blockIdx.x * BATCH + rowBase + tid] =
            part[tid * 2] + part[tid * 2 + 1];
}

// ---------------------------------------------------------------------------
// Per-row loss term (deterministic reduction over column blocks)
// ---------------------------------------------------------------------------
__global__ void k_rowloss() {
    const int r = blockIdx.x * 256 + threadIdx.x;
    float s = 0.0f;
    #pragma unroll 8
    for (int c = 0; c < COLB; c++) s += g_partial[(size_t)c * BATCH + r];
    const float p = g_pos[r];
    g_terms[r] = -p + logf(expf(p) + s);
}

// ---------------------------------------------------------------------------
// Mean over rows
// ---------------------------------------------------------------------------
__global__ void k_final(float* __restrict__ out) {
    __shared__ float sm[1024];
    const int t = threadIdx.x;
    float s = 0.0f;
    for (int r = t; r < BATCH; r += 1024) s += g_terms[r];
    sm[t] = s;
    __syncthreads();
    for (int st = 512; st > 0; st >>= 1) {
        if (t < st) sm[t] += sm[t + st];
        __syncthreads();
    }
    if (t == 0) out[0] = sm[0] / (float)BATCH;
}

// ---------------------------------------------------------------------------
extern "C" void kernel_launch(void* const* d_in, const int* in_sizes, int n_in,
                              void* d_out, int out_size) {
    const float*     X   = (const float*)d_in[0];
    const float*     Y   = (const float*)d_in[1];
    const long long* ids = (const long long*)d_in[2];
    const float*     q   = (const float*)d_in[3];

    __nv_bfloat16 *xh, *xl, *yh, *yl;
    cudaGetSymbolAddress((void**)&xh, g_Xh);
    cudaGetSymbolAddress((void**)&xl, g_Xl);
    cudaGetSymbolAddress((void**)&yh, g_Yh);
    cudaGetSymbolAddress((void**)&yl, g_Yl);

    const int np = BATCH * DIM / 2;
    k_split2<<<(np + 255) / 256, 256>>>(X, xh, xl);
    k_split2<<<(np + 255) / 256, 256>>>(Y, yh, yl);
    k_rowstats<<<BATCH, 256>>>(X, Y, ids, q);
    dim3 grid(COLB, BATCH / TM);
    k_main<<<grid, 256>>>(ids);
    k_rowloss<<<BATCH / 256, 256>>>();
    k_final<<<1, 1024>>>((float*)d_out);
}

// round 9
// speedup vs baseline: 1.7196x; 1.2899x over previous
#include <cuda_runtime.h>
#include <cuda_bf16.h>
#include <mma.h>
#include <cstdint>
#include <math.h>

using namespace nvcuda;

#define BATCH 8192
#define DIM   256
#define TM    128
#define TN    128
#define KCHUNK 32
#define NCHUNK (DIM / KCHUNK)     // 8
#define COLB  (BATCH / TN)        // 64
#define LDE   40                  // tile leading dim (elems): 80B rows, conflict-free LDSM
#define TILE_ELEMS (128 * LDE)    // 5120 bf16 = 10240 B per tile

// ---------------- static device scratch ------------------------------------
__device__ float g_rowc[BATCH];
__device__ float g_colc[BATCH];
__device__ float g_pos[BATCH];
__device__ float g_partial[COLB * BATCH];
__device__ float g_terms[BATCH];
__device__ __align__(16) __nv_bfloat16 g_Xh[BATCH * DIM];
__device__ __align__(16) __nv_bfloat16 g_Xl[BATCH * DIM];
__device__ __align__(16) __nv_bfloat16 g_Yh[BATCH * DIM];
__device__ __align__(16) __nv_bfloat16 g_Yl[BATCH * DIM];

// ---------------------------------------------------------------------------
// Split fp32 -> bf16 hi/lo pairs
// ---------------------------------------------------------------------------
__global__ void k_split2(const float* __restrict__ src, __nv_bfloat16* __restrict__ dh,
                         __nv_bfloat16* __restrict__ dl) {
    int t = blockIdx.x * blockDim.x + threadIdx.x;   // pair index
    const int np = BATCH * DIM / 2;
    if (t >= np) return;
    const float2 v = reinterpret_cast<const float2*>(src)[t];
    __nv_bfloat162 h = __floats2bfloat162_rn(v.x, v.y);
    const float h0 = __bfloat162float(__low2bfloat16(h));
    const float h1 = __bfloat162float(__high2bfloat16(h));
    __nv_bfloat162 l = __floats2bfloat162_rn(v.x - h0, v.y - h1);
    reinterpret_cast<__nv_bfloat162*>(dh)[t] = h;
    reinterpret_cast<__nv_bfloat162*>(dl)[t] = l;
}

// ---------------------------------------------------------------------------
// Per-row stats
// ---------------------------------------------------------------------------
__global__ void k_rowstats(const float* __restrict__ X, const float* __restrict__ Y,
                           const long long* __restrict__ ids, const float* __restrict__ q) {
    __shared__ int   s_cnt[256];
    __shared__ float s_pos[256];
    const int i = blockIdx.x;
    const int t = threadIdx.x;
    const long long myid = ids[i];
    int cnt = 0;
    #pragma unroll 4
    for (int j = t; j < BATCH; j += 256) cnt += (ids[j] == myid) ? 1 : 0;
    float p = X[(size_t)i * DIM + t] * Y[(size_t)i * DIM + t];
    s_cnt[t] = cnt; s_pos[t] = p;
    __syncthreads();
    for (int s = 128; s > 0; s >>= 1) {
        if (t < s) { s_cnt[t] += s_cnt[t + s]; s_pos[t] += s_pos[t + s]; }
        __syncthreads();
    }
    if (t == 0) {
        const int n_miss = BATCH - s_cnt[0];
        const float qi = q[i];
        g_rowc[i] = logf((float)n_miss) - logf(1.0f - qi);
        g_colc[i] = logf(qi);
        g_pos[i]  = s_pos[0];
    }
}

// ---------------------------------------------------------------------------
// Main: WMMA split-bf16 GEMM + fused masked-exp.
// 128x128 CTA tile, 512 threads / 16 warps (4x4), warp tile 32x32.
// Static smem ~45KB, LDG register prefetch (4 x uint4 per thread).
// ---------------------------------------------------------------------------
__global__ __launch_bounds__(512, 1)
void k_main(const long long* __restrict__ ids) {
    __shared__ __align__(128) __nv_bfloat16 tiles[4 * TILE_ELEMS];   // 40960 B
    __shared__ float     s_rc[128];
    __shared__ float     s_cq[128];
    __shared__ long long s_rid[128];
    __shared__ long long s_cid[128];
    __shared__ float     part[128 * 4];

    __nv_bfloat16* sAh = tiles;
    __nv_bfloat16* sAl = tiles + TILE_ELEMS;
    __nv_bfloat16* sBh = tiles + 2 * TILE_ELEMS;
    __nv_bfloat16* sBl = tiles + 3 * TILE_ELEMS;

    const int tid  = threadIdx.x;
    const int wid  = tid >> 5;
    const int lane = tid & 31;
    const int wm   = wid & 3;           // 0..3 : 32-row band
    const int wn   = wid >> 2;          // 0..3 : 32-col band
    const int rowBase = blockIdx.y * TM;
    const int colBase = blockIdx.x * TN;

    if (tid < 128) {
        s_rc[tid]  = g_rowc[rowBase + tid];
        s_cq[tid]  = g_colc[colBase + tid];
        s_rid[tid] = ids[rowBase + tid];
        s_cid[tid] = ids[colBase + tid];
    }

    wmma::fragment<wmma::accumulator, 16, 16, 16, float> acc[2][2];
    #pragma unroll
    for (int i = 0; i < 2; i++)
        #pragma unroll
        for (int j = 0; j < 2; j++) wmma::fill_fragment(acc[i][j], 0.0f);

    // prefetch: 2048 uint4 per chunk / 512 threads = 4 each (one per tile m)
    const int r0 = tid >> 2;                 // 0..127
    const int sg = tid & 3;                  // 0..3 : 8-elem segment
    uint4 pf[4];

    auto ldg_chunk = [&](int chunk) {
        const __nv_bfloat16* srcs[4] = {g_Xh, g_Xl, g_Yh, g_Yl};
        #pragma unroll
        for (int m = 0; m < 4; m++) {
            const int gbase = (m < 2) ? rowBase : colBase;
            pf[m] = *reinterpret_cast<const uint4*>(
                srcs[m] + (size_t)(gbase + r0) * DIM + chunk * KCHUNK + sg * 8);
        }
    };
    auto sts_chunk = [&]() {
        #pragma unroll
        for (int m = 0; m < 4; m++)
            *reinterpret_cast<uint4*>(tiles + m * TILE_ELEMS + r0 * LDE + sg * 8) = pf[m];
    };

    ldg_chunk(0);
    sts_chunk();
    __syncthreads();

    for (int c = 0; c < NCHUNK; c++) {
        if (c + 1 < NCHUNK) ldg_chunk(c + 1);

        #pragma unroll
        for (int ks = 0; ks < 2; ks++) {
            wmma::fragment<wmma::matrix_a, 16, 16, 16, __nv_bfloat16, wmma::row_major> aH[2], aL[2];
            #pragma unroll
            for (int i = 0; i < 2; i++) {
                const int ro = (wm * 32 + i * 16) * LDE + ks * 16;
                wmma::load_matrix_sync(aH[i], sAh + ro, LDE);
                wmma::load_matrix_sync(aL[i], sAl + ro, LDE);
            }
            #pragma unroll
            for (int j = 0; j < 2; j++) {
                wmma::fragment<wmma::matrix_b, 16, 16, 16, __nv_bfloat16, wmma::col_major> bH, bL;
                const int co = (wn * 32 + j * 16) * LDE + ks * 16;
                wmma::load_matrix_sync(bH, sBh + co, LDE);
                wmma::load_matrix_sync(bL, sBl + co, LDE);
                #pragma unroll
                for (int i = 0; i < 2; i++) {
                    wmma::mma_sync(acc[i][j], aH[i], bH, acc[i][j]);
                    wmma::mma_sync(acc[i][j], aH[i], bL, acc[i][j]);
                    wmma::mma_sync(acc[i][j], aL[i], bH, acc[i][j]);
                }
            }
        }
        __syncthreads();
        if (c + 1 < NCHUNK) {
            sts_chunk();
            __syncthreads();
        }
    }

    // ---- epilogue: per-warp 16x40 fp32 slab (reuses tiles), masked exp ----
    float* slab = reinterpret_cast<float*>(tiles) + wid * 640;   // 16 rows x ld 40
    const int erow = lane >> 1;          // 0..15
    const int eh   = lane & 1;           // half-row: cols eh*16 .. +15
    float rowsum[2] = {0.0f, 0.0f};

    #pragma unroll
    for (int i = 0; i < 2; i++) {        // two 16-row blocks
        wmma::store_matrix_sync(slab,      acc[i][0], LDE, wmma::mem_row_major);
        wmma::store_matrix_sync(slab + 16, acc[i][1], LDE, wmma::mem_row_major);
        __syncwarp();
        const int lrow = wm * 32 + i * 16 + erow;
        const long long idr = s_rid[lrow];
        const float rc = s_rc[lrow];
        float s = 0.0f;
        #pragma unroll
        for (int c4 = 0; c4 < 4; c4++) {
            const int cc = (c4 + erow) & 3;          // rotate: spread banks
            const float4 v = *reinterpret_cast<const float4*>(
                slab + erow * LDE + eh * 16 + cc * 4);
            const int cb = wn * 32 + eh * 16 + cc * 4;
            const float vv[4] = {v.x, v.y, v.z, v.w};
            #pragma unroll
            for (int e = 0; e < 4; e++) {
                const int col = cb + e;
                if (s_cid[col] != idr)
                    s += __expf(vv[e] - rc - s_cq[col]);
            }
        }
        rowsum[i] = s;
        __syncwarp();
    }
    #pragma unroll
    for (int i = 0; i < 2; i++) {
        float s = rowsum[i] + __shfl_xor_sync(0xFFFFFFFFu, rowsum[i], 1);
        if (eh == 0) part[(wm * 32 + i * 16 + erow) * 4 + wn] = s;
    }
    __syncthreads();
    if (tid < 128)
        g_partial[(size_t)blockIdx.x * BATCH + rowBase + tid] =
            part[tid * 4] + part[tid * 4 + 1] + part[tid * 4 + 2] + part[tid * 4 + 3];
}

// ---------------------------------------------------------------------------
// Per-row loss term (deterministic reduction over column blocks)
// ---------------------------------------------------------------------------
__global__ void k_rowloss() {
    const int r = blockIdx.x * 256 + threadIdx.x;
    float s = 0.0f;
    #pragma unroll 8
    for (int c = 0; c < COLB; c++) s += g_partial[(size_t)c * BATCH + r];
    const float p = g_pos[r];
    g_terms[r] = -p + logf(expf(p) + s);
}

// ---------------------------------------------------------------------------
// Mean over rows
// ---------------------------------------------------------------------------
__global__ void k_final(float* __restrict__ out) {
    __shared__ float sm[1024];
    const int t = threadIdx.x;
    float s = 0.0f;
    for (int r = t; r < BATCH; r += 1024) s += g_terms[r];
    sm[t] = s;
    __syncthreads();
    for (int st = 512; st > 0; st >>= 1) {
        if (t < st) sm[t] += sm[t + st];
        __syncthreads();
    }
    if (t == 0) out[0] = sm[0] / (float)BATCH;
}

// ---------------------------------------------------------------------------
extern "C" void kernel_launch(void* const* d_in, const int* in_sizes, int n_in,
                              void* d_out, int out_size) {
    const float*     X   = (const float*)d_in[0];
    const float*     Y   = (const float*)d_in[1];
    const long long* ids = (const long long*)d_in[2];
    const float*     q   = (const float*)d_in[3];

    __nv_bfloat16 *xh, *xl, *yh, *yl;
    cudaGetSymbolAddress((void**)&xh, g_Xh);
    cudaGetSymbolAddress((void**)&xl, g_Xl);
    cudaGetSymbolAddress((void**)&yh, g_Yh);
    cudaGetSymbolAddress((void**)&yl, g_Yl);

    const int np = BATCH * DIM / 2;
    k_split2<<<(np + 255) / 256, 256>>>(X, xh, xl);
    k_split2<<<(np + 255) / 256, 256>>>(Y, yh, yl);
    k_rowstats<<<BATCH, 256>>>(X, Y, ids, q);
    dim3 grid(COLB, BATCH / TM);
    k_main<<<grid, 512>>>(ids);
    k_rowloss<<<BATCH / 256, 256>>>();
    k_final<<<1, 1024>>>((float*)d_out);
}

// round 12
// speedup vs baseline: 2.1404x; 1.2447x over previous
#include <cuda_runtime.h>
#include <cuda_bf16.h>
#include <mma.h>
#include <cstdint>
#include <math.h>

using namespace nvcuda;

#define BATCH 8192
#define DIM   256
#define TM    128
#define TN    128
#define KCHUNK 32
#define NCHUNK (DIM / KCHUNK)     // 8
#define COLB  (BATCH / TN)        // 64
#define LDE   40                  // tile leading dim (elems): 80B rows, conflict-free LDSM
#define TILE_ELEMS (128 * LDE)    // 5120 bf16 = 10240 B per tile

// ---------------- static device scratch ------------------------------------
__device__ float g_rowc[BATCH];
__device__ float g_colc[BATCH];
__device__ float g_pos[BATCH];
__device__ float g_partial[COLB * BATCH];
__device__ float g_terms[BATCH];
__device__ __align__(16) __nv_bfloat16 g_Xh[BATCH * DIM];
__device__ __align__(16) __nv_bfloat16 g_Yh[BATCH * DIM];
__device__ __align__(16) __nv_bfloat16 g_Yl[BATCH * DIM];

// ---------------------------------------------------------------------------
// Splits: X -> hi only; Y -> hi + lo
// ---------------------------------------------------------------------------
__global__ void k_splitX(const float* __restrict__ src, __nv_bfloat16* __restrict__ dh) {
    int t = blockIdx.x * blockDim.x + threadIdx.x;
    const int np = BATCH * DIM / 2;
    if (t >= np) return;
    const float2 v = reinterpret_cast<const float2*>(src)[t];
    reinterpret_cast<__nv_bfloat162*>(dh)[t] = __floats2bfloat162_rn(v.x, v.y);
}
__global__ void k_splitY(const float* __restrict__ src, __nv_bfloat16* __restrict__ dh,
                         __nv_bfloat16* __restrict__ dl) {
    int t = blockIdx.x * blockDim.x + threadIdx.x;
    const int np = BATCH * DIM / 2;
    if (t >= np) return;
    const float2 v = reinterpret_cast<const float2*>(src)[t];
    __nv_bfloat162 h = __floats2bfloat162_rn(v.x, v.y);
    const float h0 = __bfloat162float(__low2bfloat16(h));
    const float h1 = __bfloat162float(__high2bfloat16(h));
    __nv_bfloat162 l = __floats2bfloat162_rn(v.x - h0, v.y - h1);
    reinterpret_cast<__nv_bfloat162*>(dh)[t] = h;
    reinterpret_cast<__nv_bfloat162*>(dl)[t] = l;
}

// ---------------------------------------------------------------------------
// Per-row stats (proven-passing version)
// ---------------------------------------------------------------------------
__global__ void k_rowstats(const float* __restrict__ X, const float* __restrict__ Y,
                           const long long* __restrict__ ids, const float* __restrict__ q) {
    __shared__ int   s_cnt[256];
    __shared__ float s_pos[256];
    const int i = blockIdx.x;
    const int t = threadIdx.x;
    const long long myid = ids[i];
    int cnt = 0;
    #pragma unroll 4
    for (int j = t; j < BATCH; j += 256) cnt += (ids[j] == myid) ? 1 : 0;
    float p = X[(size_t)i * DIM + t] * Y[(size_t)i * DIM + t];
    s_cnt[t] = cnt; s_pos[t] = p;
    __syncthreads();
    for (int s = 128; s > 0; s >>= 1) {
        if (t < s) { s_cnt[t] += s_cnt[t + s]; s_pos[t] += s_pos[t + s]; }
        __syncthreads();
    }
    if (t == 0) {
        const int n_miss = BATCH - s_cnt[0];
        const float qi = q[i];
        g_rowc[i] = logf((float)n_miss) - logf(1.0f - qi);
        g_colc[i] = logf(qi);
        g_pos[i]  = s_pos[0];
    }
}

// ---------------------------------------------------------------------------
// Main: WMMA 2-product GEMM (xh*yh + xh*yl) + fused masked-exp.
// 128x128 CTA tile, 512 threads / 16 warps (4x4), warp tile 32x32.
// Static smem (~46KB; tiles kept at 4-tile size for epilogue slab reuse).
// ---------------------------------------------------------------------------
__global__ __launch_bounds__(512, 1)
void k_main(const long long* __restrict__ ids) {
    __shared__ __align__(128) __nv_bfloat16 tiles[4 * TILE_ELEMS];   // 40960 B
    __shared__ float     s_rc[128];
    __shared__ float     s_cq[128];
    __shared__ long long s_rid[128];
    __shared__ long long s_cid[128];
    __shared__ float     part[128 * 4];

    __nv_bfloat16* sAh = tiles;
    __nv_bfloat16* sBh = tiles + TILE_ELEMS;
    __nv_bfloat16* sBl = tiles + 2 * TILE_ELEMS;

    const int tid  = threadIdx.x;
    const int wid  = tid >> 5;
    const int lane = tid & 31;
    const int wm   = wid & 3;           // 0..3 : 32-row band
    const int wn   = wid >> 2;          // 0..3 : 32-col band
    const int rowBase = blockIdx.y * TM;
    const int colBase = blockIdx.x * TN;

    if (tid < 128) {
        s_rc[tid]  = g_rowc[rowBase + tid];
        s_cq[tid]  = g_colc[colBase + tid];
        s_rid[tid] = ids[rowBase + tid];
        s_cid[tid] = ids[colBase + tid];
    }

    wmma::fragment<wmma::accumulator, 16, 16, 16, float> acc[2][2];
    #pragma unroll
    for (int i = 0; i < 2; i++)
        #pragma unroll
        for (int j = 0; j < 2; j++) wmma::fill_fragment(acc[i][j], 0.0f);

    // LDG prefetch: 3 tiles x 512 uint4 / 512 threads = 3 each
    const int r0 = tid >> 2;                 // 0..127
    const int sg = tid & 3;                  // 8-elem segment
    uint4 pf[3];

    auto ldg_chunk = [&](int chunk) {
        pf[0] = *reinterpret_cast<const uint4*>(
            g_Xh + (size_t)(rowBase + r0) * DIM + chunk * KCHUNK + sg * 8);
        pf[1] = *reinterpret_cast<const uint4*>(
            g_Yh + (size_t)(colBase + r0) * DIM + chunk * KCHUNK + sg * 8);
        pf[2] = *reinterpret_cast<const uint4*>(
            g_Yl + (size_t)(colBase + r0) * DIM + chunk * KCHUNK + sg * 8);
    };
    auto sts_chunk = [&]() {
        *reinterpret_cast<uint4*>(sAh + r0 * LDE + sg * 8) = pf[0];
        *reinterpret_cast<uint4*>(sBh + r0 * LDE + sg * 8) = pf[1];
        *reinterpret_cast<uint4*>(sBl + r0 * LDE + sg * 8) = pf[2];
    };

    ldg_chunk(0);
    sts_chunk();
    __syncthreads();

    for (int c = 0; c < NCHUNK; c++) {
        if (c + 1 < NCHUNK) ldg_chunk(c + 1);

        #pragma unroll
        for (int ks = 0; ks < 2; ks++) {
            wmma::fragment<wmma::matrix_a, 16, 16, 16, __nv_bfloat16, wmma::row_major> aH[2];
            #pragma unroll
            for (int i = 0; i < 2; i++)
                wmma::load_matrix_sync(aH[i], sAh + (wm * 32 + i * 16) * LDE + ks * 16, LDE);
            #pragma unroll
            for (int j = 0; j < 2; j++) {
                wmma::fragment<wmma::matrix_b, 16, 16, 16, __nv_bfloat16, wmma::col_major> bH, bL;
                const int co = (wn * 32 + j * 16) * LDE + ks * 16;
                wmma::load_matrix_sync(bH, sBh + co, LDE);
                wmma::load_matrix_sync(bL, sBl + co, LDE);
                #pragma unroll
                for (int i = 0; i < 2; i++) {
                    wmma::mma_sync(acc[i][j], aH[i], bH, acc[i][j]);
                    wmma::mma_sync(acc[i][j], aH[i], bL, acc[i][j]);
                }
            }
        }
        __syncthreads();
        if (c + 1 < NCHUNK) {
            sts_chunk();
            __syncthreads();
        }
    }

    // ---- epilogue: per-warp 16x40 fp32 slab (reuses tiles), masked exp ----
    float* slab = reinterpret_cast<float*>(tiles) + wid * 640;   // 16 rows x ld 40
    const int erow = lane >> 1;          // 0..15
    const int eh   = lane & 1;           // half-row: cols eh*16 .. +15
    float rowsum[2] = {0.0f, 0.0f};

    #pragma unroll
    for (int i = 0; i < 2; i++) {
        wmma::store_matrix_sync(slab,      acc[i][0], LDE, wmma::mem_row_major);
        wmma::store_matrix_sync(slab + 16, acc[i][1], LDE, wmma::mem_row_major);
        __syncwarp();
        const int lrow = wm * 32 + i * 16 + erow;
        const long long idr = s_rid[lrow];
        const float rc = s_rc[lrow];
        float s = 0.0f;
        #pragma unroll
        for (int c4 = 0; c4 < 4; c4++) {
            const int cc = (c4 + erow) & 3;
            const float4 v = *reinterpret_cast<const float4*>(
                slab + erow * LDE + eh * 16 + cc * 4);
            const int cb = wn * 32 + eh * 16 + cc * 4;
            const float vv[4] = {v.x, v.y, v.z, v.w};
            #pragma unroll
            for (int e = 0; e < 4; e++) {
                const int col = cb + e;
                if (s_cid[col] != idr)
                    s += __expf(vv[e] - rc - s_cq[col]);
            }
        }
        rowsum[i] = s;
        __syncwarp();
    }
    #pragma unroll
    for (int i = 0; i < 2; i++) {
        float s = rowsum[i] + __shfl_xor_sync(0xFFFFFFFFu, rowsum[i], 1);
        if (eh == 0) part[(wm * 32 + i * 16 + erow) * 4 + wn] = s;
    }
    __syncthreads();
    if (tid < 128)
        g_partial[(size_t)blockIdx.x * BATCH + rowBase + tid] =
            part[tid * 4] + part[tid * 4 + 1] + part[tid * 4 + 2] + part[tid * 4 + 3];
}

// ---------------------------------------------------------------------------
// Per-row loss term (deterministic reduction over column blocks)
// ---------------------------------------------------------------------------
__global__ void k_rowloss() {
    const int r = blockIdx.x * 256 + threadIdx.x;
    float s = 0.0f;
    #pragma unroll 8
    for (int c = 0; c < COLB; c++) s += g_partial[(size_t)c * BATCH + r];
    const float p = g_pos[r];
    g_terms[r] = -p + logf(expf(p) + s);
}

// ---------------------------------------------------------------------------
// Mean over rows
// ---------------------------------------------------------------------------
__global__ void k_final(float* __restrict__ out) {
    __shared__ float sm[1024];
    const int t = threadIdx.x;
    float s = 0.0f;
    for (int r = t; r < BATCH; r += 1024) s += g_terms[r];
    sm[t] = s;
    __syncthreads();
    for (int st = 512; st > 0; st >>= 1) {
        if (t < st) sm[t] += sm[t + st];
        __syncthreads();
    }
    if (t == 0) out[0] = sm[0] / (float)BATCH;
}

// ---------------------------------------------------------------------------
extern "C" void kernel_launch(void* const* d_in, const int* in_sizes, int n_in,
                              void* d_out, int out_size) {
    const float*     X   = (const float*)d_in[0];
    const float*     Y   = (const float*)d_in[1];
    const long long* ids = (const long long*)d_in[2];
    const float*     q   = (const float*)d_in[3];

    __nv_bfloat16 *xh, *yh, *yl;
    cudaGetSymbolAddress((void**)&xh, g_Xh);
    cudaGetSymbolAddress((void**)&yh, g_Yh);
    cudaGetSymbolAddress((void**)&yl, g_Yl);

    const int np = BATCH * DIM / 2;
    k_splitX<<<(np + 255) / 256, 256>>>(X, xh);
    k_splitY<<<(np + 255) / 256, 256>>>(Y, yh, yl);
    k_rowstats<<<BATCH, 256>>>(X, Y, ids, q);
    dim3 grid(COLB, BATCH / TM);
    k_main<<<grid, 512>>>(ids);
    k_rowloss<<<BATCH / 256, 256>>>();
    k_final<<<1, 1024>>>((float*)d_out);
}

// round 13
// speedup vs baseline: 2.3910x; 1.1171x over previous
#include <cuda_runtime.h>
#include <cuda_bf16.h>
#include <cuda_pipeline.h>
#include <mma.h>
#include <cstdint>
#include <math.h>

using namespace nvcuda;

#define BATCH 8192
#define DIM   256
#define TM    256
#define TN    128
#define KCHUNK 32
#define NCHUNK (DIM / KCHUNK)     // 8
#define COLB  (BATCH / TN)        // 64 column blocks
#define ROWB  (BATCH / TM)        // 32 row blocks
#define LDE   40                  // tile leading dim (elems): 80B rows, conflict-free LDSM
#define XT_ELEMS (256 * LDE)      // 10240 elems (20480 B)
#define YT_ELEMS (128 * LDE)      // 5120 elems  (10240 B)

// ---------------- static device scratch ------------------------------------
__device__ float g_rowc[BATCH];
__device__ float g_colc[BATCH];
__device__ float g_pos[BATCH];
__device__ float g_partial[COLB * BATCH];
__device__ float g_terms[BATCH];
__device__ __align__(16) __nv_bfloat16 g_Xh[BATCH * DIM];
__device__ __align__(16) __nv_bfloat16 g_Yh[BATCH * DIM];
__device__ __align__(16) __nv_bfloat16 g_Yl[BATCH * DIM];

// ---------------------------------------------------------------------------
// Splits: X -> hi only; Y -> hi + lo
// ---------------------------------------------------------------------------
__global__ void k_splitX(const float* __restrict__ src, __nv_bfloat16* __restrict__ dh) {
    int t = blockIdx.x * blockDim.x + threadIdx.x;
    const int np = BATCH * DIM / 2;
    if (t >= np) return;
    const float2 v = reinterpret_cast<const float2*>(src)[t];
    reinterpret_cast<__nv_bfloat162*>(dh)[t] = __floats2bfloat162_rn(v.x, v.y);
}
__global__ void k_splitY(const float* __restrict__ src, __nv_bfloat16* __restrict__ dh,
                         __nv_bfloat16* __restrict__ dl) {
    int t = blockIdx.x * blockDim.x + threadIdx.x;
    const int np = BATCH * DIM / 2;
    if (t >= np) return;
    const float2 v = reinterpret_cast<const float2*>(src)[t];
    __nv_bfloat162 h = __floats2bfloat162_rn(v.x, v.y);
    const float h0 = __bfloat162float(__low2bfloat16(h));
    const float h1 = __bfloat162float(__high2bfloat16(h));
    __nv_bfloat162 l = __floats2bfloat162_rn(v.x - h0, v.y - h1);
    reinterpret_cast<__nv_bfloat162*>(dh)[t] = h;
    reinterpret_cast<__nv_bfloat162*>(dl)[t] = l;
}

// ---------------------------------------------------------------------------
// Per-row stats (proven-passing version)
// ---------------------------------------------------------------------------
__global__ void k_rowstats(const float* __restrict__ X, const float* __restrict__ Y,
                           const long long* __restrict__ ids, const float* __restrict__ q) {
    __shared__ int   s_cnt[256];
    __shared__ float s_pos[256];
    const int i = blockIdx.x;
    const int t = threadIdx.x;
    const long long myid = ids[i];
    int cnt = 0;
    #pragma unroll 4
    for (int j = t; j < BATCH; j += 256) cnt += (ids[j] == myid) ? 1 : 0;
    float p = X[(size_t)i * DIM + t] * Y[(size_t)i * DIM + t];
    s_cnt[t] = cnt; s_pos[t] = p;
    __syncthreads();
    for (int s = 128; s > 0; s >>= 1) {
        if (t < s) { s_cnt[t] += s_cnt[t + s]; s_pos[t] += s_pos[t + s]; }
        __syncthreads();
    }
    if (t == 0) {
        const int n_miss = BATCH - s_cnt[0];
        const float qi = q[i];
        g_rowc[i] = logf((float)n_miss) - logf(1.0f - qi);
        g_colc[i] = logf(qi);
        g_pos[i]  = s_pos[0];
    }
}

// ---------------------------------------------------------------------------
// Main: WMMA 2-product GEMM (xh*yh + xh*yl) + fused masked-exp.
// 256x128 CTA tile, 512 threads / 16 warps (4x4), warp tile 64x32.
// Single-stage static smem (47KB), cp.async (LDGSTS) tile fill.
// ---------------------------------------------------------------------------
__global__ __launch_bounds__(512, 1)
void k_main(const long long* __restrict__ ids) {
    __shared__ __align__(128) __nv_bfloat16 tiles[XT_ELEMS + 2 * YT_ELEMS]; // 40960 B
    __shared__ float part[256 * 4];           // 4096 B
    __shared__ float s_rc[256];               // 1024 B
    __shared__ float s_cq[128];               // 512 B
    __shared__ int   s_rid[256];              // 1024 B
    __shared__ int   s_cid[128];              // 512 B

    __nv_bfloat16* sX  = tiles;
    __nv_bfloat16* sYh = tiles + XT_ELEMS;
    __nv_bfloat16* sYl = tiles + XT_ELEMS + YT_ELEMS;

    const int tid  = threadIdx.x;
    const int wid  = tid >> 5;
    const int lane = tid & 31;
    const int wm   = wid >> 2;          // 0..3 : 64-row band
    const int wn   = wid & 3;           // 0..3 : 32-col band
    const int rowBase = blockIdx.y * TM;
    const int colBase = blockIdx.x * TN;

    if (tid < 256) {
        s_rc[tid]  = g_rowc[rowBase + tid];
        s_rid[tid] = (int)ids[rowBase + tid];
    }
    if (tid < 128) {
        s_cq[tid]  = g_colc[colBase + tid];
        s_cid[tid] = (int)ids[colBase + tid];
    }

    wmma::fragment<wmma::accumulator, 16, 16, 16, float> acc[4][2];
    #pragma unroll
    for (int i = 0; i < 4; i++)
        #pragma unroll
        for (int j = 0; j < 2; j++) wmma::fill_fragment(acc[i][j], 0.0f);

    const int rr = tid >> 2;                 // 0..127
    const int sg = tid & 3;                  // 8-elem (16B) segment

    auto issue_chunk = [&](int chunk) {
        const int kbase = chunk * KCHUNK + sg * 8;
        // X rows 0..127 and 128..255
        __pipeline_memcpy_async(sX + rr * LDE + sg * 8,
            g_Xh + (size_t)(rowBase + rr) * DIM + kbase, 16);
        __pipeline_memcpy_async(sX + (128 + rr) * LDE + sg * 8,
            g_Xh + (size_t)(rowBase + 128 + rr) * DIM + kbase, 16);
        // Yh, Yl rows 0..127
        __pipeline_memcpy_async(sYh + rr * LDE + sg * 8,
            g_Yh + (size_t)(colBase + rr) * DIM + kbase, 16);
        __pipeline_memcpy_async(sYl + rr * LDE + sg * 8,
            g_Yl + (size_t)(colBase + rr) * DIM + kbase, 16);
        __pipeline_commit();
    };

    issue_chunk(0);

    for (int c = 0; c < NCHUNK; c++) {
        __pipeline_wait_prior(0);
        __syncthreads();

        #pragma unroll
        for (int ks = 0; ks < 2; ks++) {
            wmma::fragment<wmma::matrix_b, 16, 16, 16, __nv_bfloat16, wmma::col_major> bH[2], bL[2];
            #pragma unroll
            for (int j = 0; j < 2; j++) {
                const int co = (wn * 32 + j * 16) * LDE + ks * 16;
                wmma::load_matrix_sync(bH[j], sYh + co, LDE);
                wmma::load_matrix_sync(bL[j], sYl + co, LDE);
            }
            #pragma unroll
            for (int i = 0; i < 4; i++) {
                wmma::fragment<wmma::matrix_a, 16, 16, 16, __nv_bfloat16, wmma::row_major> aH;
                wmma::load_matrix_sync(aH, sX + (wm * 64 + i * 16) * LDE + ks * 16, LDE);
                #pragma unroll
                for (int j = 0; j < 2; j++) {
                    wmma::mma_sync(acc[i][j], aH, bH[j], acc[i][j]);
                    wmma::mma_sync(acc[i][j], aH, bL[j], acc[i][j]);
                }
            }
        }
        __syncthreads();
        if (c + 1 < NCHUNK) issue_chunk(c + 1);
    }

    // ---- epilogue: per-warp 16x40 fp32 slab (reuses tiles), masked exp ----
    float* slab = reinterpret_cast<float*>(tiles) + wid * 640;   // 16 rows x ld 40
    const int erow = lane >> 1;          // 0..15
    const int eh   = lane & 1;           // half-row: cols eh*16 .. +15

    #pragma unroll
    for (int i = 0; i < 4; i++) {
        wmma::store_matrix_sync(slab,      acc[i][0], LDE, wmma::mem_row_major);
        wmma::store_matrix_sync(slab + 16, acc[i][1], LDE, wmma::mem_row_major);
        __syncwarp();
        const int lrow = wm * 64 + i * 16 + erow;
        const int idr = s_rid[lrow];
        const float rc = s_rc[lrow];
        float s = 0.0f;
        #pragma unroll
        for (int c4 = 0; c4 < 4; c4++) {
            const int cc = (c4 + erow) & 3;
            const float4 v = *reinterpret_cast<const float4*>(
                slab + erow * LDE + eh * 16 + cc * 4);
            const int cb = wn * 32 + eh * 16 + cc * 4;
            const float vv[4] = {v.x, v.y, v.z, v.w};
            #pragma unroll
            for (int e = 0; e < 4; e++) {
                const int col = cb + e;
                if (s_cid[col] != idr)
                    s += __expf(vv[e] - rc - s_cq[col]);
            }
        }
        s += __shfl_xor_sync(0xFFFFFFFFu, s, 1);
        if (eh == 0) part[lrow * 4 + wn] = s;
        __syncwarp();
    }
    __syncthreads();
    if (tid < 256)
        g_partial[(size_t)blockIdx.x * BATCH + rowBase + tid] =
            part[tid * 4] + part[tid * 4 + 1] + part[tid * 4 + 2] + part[tid * 4 + 3];
}

// ---------------------------------------------------------------------------
// Per-row loss term (deterministic reduction over column blocks)
// ---------------------------------------------------------------------------
__global__ void k_rowloss() {
    const int r = blockIdx.x * 256 + threadIdx.x;
    float s = 0.0f;
    #pragma unroll 8
    for (int c = 0; c < COLB; c++) s += g_partial[(size_t)c * BATCH + r];
    const float p = g_pos[r];
    g_terms[r] = -p + logf(expf(p) + s);
}

// ---------------------------------------------------------------------------
// Mean over rows
// ---------------------------------------------------------------------------
__global__ void k_final(float* __restrict__ out) {
    __shared__ float sm[1024];
    const int t = threadIdx.x;
    float s = 0.0f;
    for (int r = t; r < BATCH; r += 1024) s += g_terms[r];
    sm[t] = s;
    __syncthreads();
    for (int st = 512; st > 0; st >>= 1) {
        if (t < st) sm[t] += sm[t + st];
        __syncthreads();
    }
    if (t == 0) out[0] = sm[0] / (float)BATCH;
}

// ---------------------------------------------------------------------------
extern "C" void kernel_launch(void* const* d_in, const int* in_sizes, int n_in,
                              void* d_out, int out_size) {
    const float*     X   = (const float*)d_in[0];
    const float*     Y   = (const float*)d_in[1];
    const long long* ids = (const long long*)d_in[2];
    const float*     q   = (const float*)d_in[3];

    __nv_bfloat16 *xh, *yh, *yl;
    cudaGetSymbolAddress((void**)&xh, g_Xh);
    cudaGetSymbolAddress((void**)&yh, g_Yh);
    cudaGetSymbolAddress((void**)&yl, g_Yl);

    const int np = BATCH * DIM / 2;
    k_splitX<<<(np + 255) / 256, 256>>>(X, xh);
    k_splitY<<<(np + 255) / 256, 256>>>(Y, yh, yl);
    k_rowstats<<<BATCH, 256>>>(X, Y, ids, q);
    dim3 grid(COLB, ROWB);
    k_main<<<grid, 512>>>(ids);
    k_rowloss<<<BATCH / 256, 256>>>();
    k_final<<<1, 1024>>>((float*)d_out);
}

// round 14
// speedup vs baseline: 2.5261x; 1.0565x over previous
#include <cuda_runtime.h>
#include <cuda_bf16.h>
#include <cuda_pipeline.h>
#include <mma.h>
#include <cstdint>
#include <math.h>

using namespace nvcuda;

#define BATCH 8192
#define DIM   256
#define TM    256
#define TN    128
#define KCHUNK 32
#define NCHUNK (DIM / KCHUNK)     // 8
#define COLB  (BATCH / TN)        // 64 column blocks
#define ROWB  (BATCH / TM)        // 32 row blocks
#define LDE   40                  // tile leading dim (elems): 80B rows, conflict-free LDSM
#define XT_ELEMS (256 * LDE)      // 10240 elems (20480 B)
#define YT_ELEMS (128 * LDE)      // 5120 elems  (10240 B)
#define STAGE_ELEMS (XT_ELEMS + 2 * YT_ELEMS)   // 20480 elems (40960 B)
#define SMEM_DYN (2 * STAGE_ELEMS * 2)          // 81920 B

// ---------------- static device scratch ------------------------------------
__device__ float g_rowc[BATCH];
__device__ float g_colc[BATCH];
__device__ float g_pos[BATCH];
__device__ float g_partial[COLB * BATCH];
__device__ float g_terms[BATCH];
__device__ __align__(16) __nv_bfloat16 g_Xh[BATCH * DIM];
__device__ __align__(16) __nv_bfloat16 g_Yh[BATCH * DIM];
__device__ __align__(16) __nv_bfloat16 g_Yl[BATCH * DIM];

// ---------------------------------------------------------------------------
// Splits: X -> hi only; Y -> hi + lo
// ---------------------------------------------------------------------------
__global__ void k_splitX(const float* __restrict__ src, __nv_bfloat16* __restrict__ dh) {
    int t = blockIdx.x * blockDim.x + threadIdx.x;
    const int np = BATCH * DIM / 2;
    if (t >= np) return;
    const float2 v = reinterpret_cast<const float2*>(src)[t];
    reinterpret_cast<__nv_bfloat162*>(dh)[t] = __floats2bfloat162_rn(v.x, v.y);
}
__global__ void k_splitY(const float* __restrict__ src, __nv_bfloat16* __restrict__ dh,
                         __nv_bfloat16* __restrict__ dl) {
    int t = blockIdx.x * blockDim.x + threadIdx.x;
    const int np = BATCH * DIM / 2;
    if (t >= np) return;
    const float2 v = reinterpret_cast<const float2*>(src)[t];
    __nv_bfloat162 h = __floats2bfloat162_rn(v.x, v.y);
    const float h0 = __bfloat162float(__low2bfloat16(h));
    const float h1 = __bfloat162float(__high2bfloat16(h));
    __nv_bfloat162 l = __floats2bfloat162_rn(v.x - h0, v.y - h1);
    reinterpret_cast<__nv_bfloat162*>(dh)[t] = h;
    reinterpret_cast<__nv_bfloat162*>(dl)[t] = l;
}

// ---------------------------------------------------------------------------
// Per-row stats (proven-passing version)
// ---------------------------------------------------------------------------
__global__ void k_rowstats(const float* __restrict__ X, const float* __restrict__ Y,
                           const long long* __restrict__ ids, const float* __restrict__ q) {
    __shared__ int   s_cnt[256];
    __shared__ float s_pos[256];
    const int i = blockIdx.x;
    const int t = threadIdx.x;
    const long long myid = ids[i];
    int cnt = 0;
    #pragma unroll 4
    for (int j = t; j < BATCH; j += 256) cnt += (ids[j] == myid) ? 1 : 0;
    float p = X[(size_t)i * DIM + t] * Y[(size_t)i * DIM + t];
    s_cnt[t] = cnt; s_pos[t] = p;
    __syncthreads();
    for (int s = 128; s > 0; s >>= 1) {
        if (t < s) { s_cnt[t] += s_cnt[t + s]; s_pos[t] += s_pos[t + s]; }
        __syncthreads();
    }
    if (t == 0) {
        const int n_miss = BATCH - s_cnt[0];
        const float qi = q[i];
        g_rowc[i] = logf((float)n_miss) - logf(1.0f - qi);
        g_colc[i] = logf(qi);
        g_pos[i]  = s_pos[0];
    }
}

// ---------------------------------------------------------------------------
// Main: WMMA 2-product GEMM (xh*yh + xh*yl) + fused masked-exp.
// 256x128 CTA tile, 512 threads / 16 warps (4x4), warp tile 64x32.
// 2-stage double-buffered cp.async pipeline in 80KB dynamic smem.
// ---------------------------------------------------------------------------
__global__ __launch_bounds__(512, 1)
void k_main(const long long* __restrict__ ids) {
    extern __shared__ __align__(128) __nv_bfloat16 stages[];   // 2 * STAGE_ELEMS
    __shared__ float part[256 * 4];
    __shared__ float s_rc[256];
    __shared__ float s_cq[128];
    __shared__ int   s_rid[256];
    __shared__ int   s_cid[128];

    const int tid  = threadIdx.x;
    const int wid  = tid >> 5;
    const int lane = tid & 31;
    const int wm   = wid >> 2;          // 0..3 : 64-row band
    const int wn   = wid & 3;           // 0..3 : 32-col band
    const int rowBase = blockIdx.y * TM;
    const int colBase = blockIdx.x * TN;

    if (tid < 256) {
        s_rc[tid]  = g_rowc[rowBase + tid];
        s_rid[tid] = (int)ids[rowBase + tid];
    }
    if (tid < 128) {
        s_cq[tid]  = g_colc[colBase + tid];
        s_cid[tid] = (int)ids[colBase + tid];
    }

    wmma::fragment<wmma::accumulator, 16, 16, 16, float> acc[4][2];
    #pragma unroll
    for (int i = 0; i < 4; i++)
        #pragma unroll
        for (int j = 0; j < 2; j++) wmma::fill_fragment(acc[i][j], 0.0f);

    const int rr = tid >> 2;                 // 0..127
    const int sg = tid & 3;                  // 8-elem (16B) segment

    auto issue_chunk = [&](int chunk, int st) {
        __nv_bfloat16* sX  = stages + st * STAGE_ELEMS;
        __nv_bfloat16* sYh = sX + XT_ELEMS;
        __nv_bfloat16* sYl = sYh + YT_ELEMS;
        const int kbase = chunk * KCHUNK + sg * 8;
        __pipeline_memcpy_async(sX + rr * LDE + sg * 8,
            g_Xh + (size_t)(rowBase + rr) * DIM + kbase, 16);
        __pipeline_memcpy_async(sX + (128 + rr) * LDE + sg * 8,
            g_Xh + (size_t)(rowBase + 128 + rr) * DIM + kbase, 16);
        __pipeline_memcpy_async(sYh + rr * LDE + sg * 8,
            g_Yh + (size_t)(colBase + rr) * DIM + kbase, 16);
        __pipeline_memcpy_async(sYl + rr * LDE + sg * 8,
            g_Yl + (size_t)(colBase + rr) * DIM + kbase, 16);
        __pipeline_commit();
    };

    issue_chunk(0, 0);
    issue_chunk(1, 1);

    for (int c = 0; c < NCHUNK; c++) {
        if (c + 1 < NCHUNK) __pipeline_wait_prior(1);
        else                __pipeline_wait_prior(0);
        __syncthreads();

        __nv_bfloat16* sX  = stages + (c & 1) * STAGE_ELEMS;
        __nv_bfloat16* sYh = sX + XT_ELEMS;
        __nv_bfloat16* sYl = sYh + YT_ELEMS;

        #pragma unroll
        for (int ks = 0; ks < 2; ks++) {
            wmma::fragment<wmma::matrix_b, 16, 16, 16, __nv_bfloat16, wmma::col_major> bH[2], bL[2];
            #pragma unroll
            for (int j = 0; j < 2; j++) {
                const int co = (wn * 32 + j * 16) * LDE + ks * 16;
                wmma::load_matrix_sync(bH[j], sYh + co, LDE);
                wmma::load_matrix_sync(bL[j], sYl + co, LDE);
            }
            #pragma unroll
            for (int i = 0; i < 4; i++) {
                wmma::fragment<wmma::matrix_a, 16, 16, 16, __nv_bfloat16, wmma::row_major> aH;
                wmma::load_matrix_sync(aH, sX + (wm * 64 + i * 16) * LDE + ks * 16, LDE);
                #pragma unroll
                for (int j = 0; j < 2; j++) {
                    wmma::mma_sync(acc[i][j], aH, bH[j], acc[i][j]);
                    wmma::mma_sync(acc[i][j], aH, bL[j], acc[i][j]);
                }
            }
        }
        __syncthreads();                       // all warps done reading stage c&1
        if (c + 2 < NCHUNK) issue_chunk(c + 2, c & 1);
    }

    // ---- epilogue: per-warp 16x40 fp32 slab (reuses stage smem), masked exp ----
    float* slab = reinterpret_cast<float*>(stages) + wid * 640;   // 16 rows x ld 40
    const int erow = lane >> 1;          // 0..15
    const int eh   = lane & 1;           // half-row: cols eh*16 .. +15

    #pragma unroll
    for (int i = 0; i < 4; i++) {
        wmma::store_matrix_sync(slab,      acc[i][0], LDE, wmma::mem_row_major);
        wmma::store_matrix_sync(slab + 16, acc[i][1], LDE, wmma::mem_row_major);
        __syncwarp();
        const int lrow = wm * 64 + i * 16 + erow;
        const int idr = s_rid[lrow];
        const float rc = s_rc[lrow];
        float s = 0.0f;
        #pragma unroll
        for (int c4 = 0; c4 < 4; c4++) {
            const int cc = (c4 + erow) & 3;
            const float4 v = *reinterpret_cast<const float4*>(
                slab + erow * LDE + eh * 16 + cc * 4);
            const int cb = wn * 32 + eh * 16 + cc * 4;
            const float vv[4] = {v.x, v.y, v.z, v.w};
            #pragma unroll
            for (int e = 0; e < 4; e++) {
                const int col = cb + e;
                if (s_cid[col] != idr)
                    s += __expf(vv[e] - rc - s_cq[col]);
            }
        }
        s += __shfl_xor_sync(0xFFFFFFFFu, s, 1);
        if (eh == 0) part[lrow * 4 + wn] = s;
        __syncwarp();
    }
    __syncthreads();
    if (tid < 256)
        g_partial[(size_t)blockIdx.x * BATCH + rowBase + tid] =
            part[tid * 4] + part[tid * 4 + 1] + part[tid * 4 + 2] + part[tid * 4 + 3];
}

// ---------------------------------------------------------------------------
// Per-row loss term (deterministic reduction over column blocks)
// ---------------------------------------------------------------------------
__global__ void k_rowloss() {
    const int r = blockIdx.x * 256 + threadIdx.x;
    float s = 0.0f;
    #pragma unroll 8
    for (int c = 0; c < COLB; c++) s += g_partial[(size_t)c * BATCH + r];
    const float p = g_pos[r];
    g_terms[r] = -p + logf(expf(p) + s);
}

// ---------------------------------------------------------------------------
// Mean over rows
// ---------------------------------------------------------------------------
__global__ void k_final(float* __restrict__ out) {
    __shared__ float sm[1024];
    const int t = threadIdx.x;
    float s = 0.0f;
    for (int r = t; r < BATCH; r += 1024) s += g_terms[r];
    sm[t] = s;
    __syncthreads();
    for (int st = 512; st > 0; st >>= 1) {
        if (t < st) sm[t] += sm[t + st];
        __syncthreads();
    }
    if (t == 0) out[0] = sm[0] / (float)BATCH;
}

// ---------------------------------------------------------------------------
extern "C" void kernel_launch(void* const* d_in, const int* in_sizes, int n_in,
                              void* d_out, int out_size) {
    const float*     X   = (const float*)d_in[0];
    const float*     Y   = (const float*)d_in[1];
    const long long* ids = (const long long*)d_in[2];
    const float*     q   = (const float*)d_in[3];

    __nv_bfloat16 *xh, *yh, *yl;
    cudaGetSymbolAddress((void**)&xh, g_Xh);
    cudaGetSymbolAddress((void**)&yh, g_Yh);
    cudaGetSymbolAddress((void**)&yl, g_Yl);

    cudaFuncSetAttribute(k_main, cudaFuncAttributeMaxDynamicSharedMemorySize, SMEM_DYN);

    const int np = BATCH * DIM / 2;
    k_splitX<<<(np + 255) / 256, 256>>>(X, xh);
    k_splitY<<<(np + 255) / 256, 256>>>(Y, yh, yl);
    k_rowstats<<<BATCH, 256>>>(X, Y, ids, q);
    dim3 grid(COLB, ROWB);
    k_main<<<grid, 512, SMEM_DYN>>>(ids);
    k_rowloss<<<BATCH / 256, 256>>>();
    k_final<<<1, 1024>>>((float*)d_out);
}

// round 15
// speedup vs baseline: 3.2534x; 1.2879x over previous
#include <cuda_runtime.h>
#include <cuda_bf16.h>
#include <cuda_pipeline.h>
#include <mma.h>
#include <cstdint>
#include <math.h>

using namespace nvcuda;

#define BATCH 8192
#define DIM   256
#define TM    256
#define TN    128
#define KCHUNK 32
#define NCHUNK (DIM / KCHUNK)     // 8
#define COLB  (BATCH / TN)        // 64 column blocks
#define ROWB  (BATCH / TM)        // 32 row blocks
#define LDE   40                  // tile leading dim (elems): 80B rows, conflict-free LDSM
#define XT_ELEMS (256 * LDE)      // 10240 elems (20480 B)
#define YT_ELEMS (128 * LDE)      // 5120 elems  (10240 B)
#define STAGE_ELEMS (XT_ELEMS + YT_ELEMS)       // 15360 elems (30720 B)
#define NSTAGE 3
#define SMEM_DYN (NSTAGE * STAGE_ELEMS * 2)     // 92160 B

// ---------------- static device scratch ------------------------------------
__device__ float g_rowc[BATCH];
__device__ float g_colc[BATCH];
__device__ float g_pos[BATCH];
__device__ float g_partial[COLB * BATCH];
__device__ float g_terms[BATCH];
__device__ __align__(16) __nv_bfloat16 g_Xh[BATCH * DIM];
__device__ __align__(16) __nv_bfloat16 g_Yh[BATCH * DIM];

// ---------------------------------------------------------------------------
// Split: fp32 -> bf16 (hi only)
// ---------------------------------------------------------------------------
__global__ void k_splitX(const float* __restrict__ src, __nv_bfloat16* __restrict__ dh) {
    int t = blockIdx.x * blockDim.x + threadIdx.x;
    const int np = BATCH * DIM / 2;
    if (t >= np) return;
    const float2 v = reinterpret_cast<const float2*>(src)[t];
    reinterpret_cast<__nv_bfloat162*>(dh)[t] = __floats2bfloat162_rn(v.x, v.y);
}

// ---------------------------------------------------------------------------
// Per-row stats (proven-passing version)
// ---------------------------------------------------------------------------
__global__ void k_rowstats(const float* __restrict__ X, const float* __restrict__ Y,
                           const long long* __restrict__ ids, const float* __restrict__ q) {
    __shared__ int   s_cnt[256];
    __shared__ float s_pos[256];
    const int i = blockIdx.x;
    const int t = threadIdx.x;
    const long long myid = ids[i];
    int cnt = 0;
    #pragma unroll 4
    for (int j = t; j < BATCH; j += 256) cnt += (ids[j] == myid) ? 1 : 0;
    float p = X[(size_t)i * DIM + t] * Y[(size_t)i * DIM + t];
    s_cnt[t] = cnt; s_pos[t] = p;
    __syncthreads();
    for (int s = 128; s > 0; s >>= 1) {
        if (t < s) { s_cnt[t] += s_cnt[t + s]; s_pos[t] += s_pos[t + s]; }
        __syncthreads();
    }
    if (t == 0) {
        const int n_miss = BATCH - s_cnt[0];
        const float qi = q[i];
        g_rowc[i] = logf((float)n_miss) - logf(1.0f - qi);
        g_colc[i] = logf(qi);
        g_pos[i]  = s_pos[0];
    }
}

// ---------------------------------------------------------------------------
// Main: WMMA bf16 GEMM (xh*yh) + fused masked-exp.
// 256x128 CTA tile, 512 threads / 16 warps (4x4), warp tile 64x32.
// 3-stage cp.async pipeline in 90KB dynamic smem.
// ---------------------------------------------------------------------------
__global__ __launch_bounds__(512, 1)
void k_main(const long long* __restrict__ ids) {
    extern __shared__ __align__(128) __nv_bfloat16 stages[];   // NSTAGE * STAGE_ELEMS
    __shared__ float part[256 * 4];
    __shared__ float s_rc[256];
    __shared__ float s_cq[128];
    __shared__ int   s_rid[256];
    __shared__ int   s_cid[128];

    const int tid  = threadIdx.x;
    const int wid  = tid >> 5;
    const int lane = tid & 31;
    const int wm   = wid >> 2;          // 0..3 : 64-row band
    const int wn   = wid & 3;           // 0..3 : 32-col band
    const int rowBase = blockIdx.y * TM;
    const int colBase = blockIdx.x * TN;

    if (tid < 256) {
        s_rc[tid]  = g_rowc[rowBase + tid];
        s_rid[tid] = (int)ids[rowBase + tid];
    }
    if (tid < 128) {
        s_cq[tid]  = g_colc[colBase + tid];
        s_cid[tid] = (int)ids[colBase + tid];
    }

    wmma::fragment<wmma::accumulator, 16, 16, 16, float> acc[4][2];
    #pragma unroll
    for (int i = 0; i < 4; i++)
        #pragma unroll
        for (int j = 0; j < 2; j++) wmma::fill_fragment(acc[i][j], 0.0f);

    const int rr = tid >> 2;                 // 0..127
    const int sg = tid & 3;                  // 8-elem (16B) segment

    auto issue_chunk = [&](int chunk, int st) {
        __nv_bfloat16* sX  = stages + st * STAGE_ELEMS;
        __nv_bfloat16* sYh = sX + XT_ELEMS;
        const int kbase = chunk * KCHUNK + sg * 8;
        __pipeline_memcpy_async(sX + rr * LDE + sg * 8,
            g_Xh + (size_t)(rowBase + rr) * DIM + kbase, 16);
        __pipeline_memcpy_async(sX + (128 + rr) * LDE + sg * 8,
            g_Xh + (size_t)(rowBase + 128 + rr) * DIM + kbase, 16);
        __pipeline_memcpy_async(sYh + rr * LDE + sg * 8,
            g_Yh + (size_t)(colBase + rr) * DIM + kbase, 16);
        __pipeline_commit();
    };

    issue_chunk(0, 0);
    issue_chunk(1, 1);
    issue_chunk(2, 2);

    for (int c = 0; c < NCHUNK; c++) {
        const int remain = NCHUNK - 1 - c;
        if (remain >= 2)      __pipeline_wait_prior(2);
        else if (remain == 1) __pipeline_wait_prior(1);
        else                  __pipeline_wait_prior(0);
        __syncthreads();

        const int st = c % NSTAGE;
        __nv_bfloat16* sX  = stages + st * STAGE_ELEMS;
        __nv_bfloat16* sYh = sX + XT_ELEMS;

        #pragma unroll
        for (int ks = 0; ks < 2; ks++) {
            wmma::fragment<wmma::matrix_b, 16, 16, 16, __nv_bfloat16, wmma::col_major> bH[2];
            #pragma unroll
            for (int j = 0; j < 2; j++)
                wmma::load_matrix_sync(bH[j], sYh + (wn * 32 + j * 16) * LDE + ks * 16, LDE);
            #pragma unroll
            for (int i = 0; i < 4; i++) {
                wmma::fragment<wmma::matrix_a, 16, 16, 16, __nv_bfloat16, wmma::row_major> aH;
                wmma::load_matrix_sync(aH, sX + (wm * 64 + i * 16) * LDE + ks * 16, LDE);
                #pragma unroll
                for (int j = 0; j < 2; j++)
                    wmma::mma_sync(acc[i][j], aH, bH[j], acc[i][j]);
            }
        }
        __syncthreads();                       // all warps done reading stage st
        if (c + 3 < NCHUNK) issue_chunk(c + 3, st);
    }

    // ---- epilogue: per-warp 16x40 fp32 slab (reuses stage smem), masked exp ----
    float* slab = reinterpret_cast<float*>(stages) + wid * 640;   // 16 rows x ld 40
    const int erow = lane >> 1;          // 0..15
    const int eh   = lane & 1;           // half-row: cols eh*16 .. +15

    #pragma unroll
    for (int i = 0; i < 4; i++) {
        wmma::store_matrix_sync(slab,      acc[i][0], LDE, wmma::mem_row_major);
        wmma::store_matrix_sync(slab + 16, acc[i][1], LDE, wmma::mem_row_major);
        __syncwarp();
        const int lrow = wm * 64 + i * 16 + erow;
        const int idr = s_rid[lrow];
        const float rc = s_rc[lrow];
        float s = 0.0f;
        #pragma unroll
        for (int c4 = 0; c4 < 4; c4++) {
            const int cc = (c4 + erow) & 3;
            const float4 v = *reinterpret_cast<const float4*>(
                slab + erow * LDE + eh * 16 + cc * 4);
            const int cb = wn * 32 + eh * 16 + cc * 4;
            const float vv[4] = {v.x, v.y, v.z, v.w};
            #pragma unroll
            for (int e = 0; e < 4; e++) {
                const int col = cb + e;
                if (s_cid[col] != idr)
                    s += __expf(vv[e] - rc - s_cq[col]);
            }
        }
        s += __shfl_xor_sync(0xFFFFFFFFu, s, 1);
        if (eh == 0) part[lrow * 4 + wn] = s;
        __syncwarp();
    }
    __syncthreads();
    if (tid < 256)
        g_partial[(size_t)blockIdx.x * BATCH + rowBase + tid] =
            part[tid * 4] + part[tid * 4 + 1] + part[tid * 4 + 2] + part[tid * 4 + 3];
}

// ---------------------------------------------------------------------------
// Per-row loss term (deterministic reduction over column blocks)
// ---------------------------------------------------------------------------
__global__ void k_rowloss() {
    const int r = blockIdx.x * 256 + threadIdx.x;
    float s = 0.0f;
    #pragma unroll 8
    for (int c = 0; c < COLB; c++) s += g_partial[(size_t)c * BATCH + r];
    const float p = g_pos[r];
    g_terms[r] = -p + logf(expf(p) + s);
}

// ---------------------------------------------------------------------------
// Mean over rows
// ---------------------------------------------------------------------------
__global__ void k_final(float* __restrict__ out) {
    __shared__ float sm[1024];
    const int t = threadIdx.x;
    float s = 0.0f;
    for (int r = t; r < BATCH; r += 1024) s += g_terms[r];
    sm[t] = s;
    __syncthreads();
    for (int st = 512; st > 0; st >>= 1) {
        if (t < st) sm[t] += sm[t + st];
        __syncthreads();
    }
    if (t == 0) out[0] = sm[0] / (float)BATCH;
}

// ---------------------------------------------------------------------------
extern "C" void kernel_launch(void* const* d_in, const int* in_sizes, int n_in,
                              void* d_out, int out_size) {
    const float*     X   = (const float*)d_in[0];
    const float*     Y   = (const float*)d_in[1];
    const long long* ids = (const long long*)d_in[2];
    const float*     q   = (const float*)d_in[3];

    __nv_bfloat16 *xh, *yh;
    cudaGetSymbolAddress((void**)&xh, g_Xh);
    cudaGetSymbolAddress((void**)&yh, g_Yh);

    cudaFuncSetAttribute(k_main, cudaFuncAttributeMaxDynamicSharedMemorySize, SMEM_DYN);

    const int np = BATCH * DIM / 2;
    k_splitX<<<(np + 255) / 256, 256>>>(X, xh);
    k_splitX<<<(np + 255) / 256, 256>>>(Y, yh);
    k_rowstats<<<BATCH, 256>>>(X, Y, ids, q);
    dim3 grid(COLB, ROWB);
    k_main<<<grid, 512, SMEM_DYN>>>(ids);
    k_rowloss<<<BATCH / 256, 256>>>();
    k_final<<<1, 1024>>>((float*)d_out);
}

// round 17
// speedup vs baseline: 3.5792x; 1.1002x over previous
#include <cuda_runtime.h>
#include <cuda_bf16.h>
#include <cuda_pipeline.h>
#include <mma.h>
#include <cstdint>
#include <math.h>

using namespace nvcuda;

#define BATCH 8192
#define DIM   256
#define TM    128
#define TN    128
#define KCHUNK 32
#define NCHUNK (DIM / KCHUNK)     // 8
#define COLB  (BATCH / TN)        // 64 column blocks
#define ROWB  (BATCH / TM)        // 64 row blocks
#define LDE   40                  // tile leading dim (elems): 80B rows, conflict-free LDSM
#define XT_ELEMS (128 * LDE)      // 5120 elems (10240 B)
#define YT_ELEMS (128 * LDE)      // 5120 elems (10240 B)
#define STAGE_ELEMS (XT_ELEMS + YT_ELEMS)       // 10240 elems (20480 B)
#define NSTAGE 3
#define SMEM_DYN (NSTAGE * STAGE_ELEMS * 2)     // 61440 B

// ---------------- static device scratch ------------------------------------
__device__ float g_rowc[BATCH];
__device__ float g_colc[BATCH];
__device__ float g_pos[BATCH];
__device__ float g_partial[COLB * BATCH];
__device__ float g_terms[BATCH];
__device__ __align__(16) __nv_bfloat16 g_Xh[BATCH * DIM];
__device__ __align__(16) __nv_bfloat16 g_Yh[BATCH * DIM];

// ---------------------------------------------------------------------------
// Split: fp32 -> bf16 (hi only)
// ---------------------------------------------------------------------------
__global__ void k_splitX(const float* __restrict__ src, __nv_bfloat16* __restrict__ dh) {
    int t = blockIdx.x * blockDim.x + threadIdx.x;
    const int np = BATCH * DIM / 2;
    if (t >= np) return;
    const float2 v = reinterpret_cast<const float2*>(src)[t];
    reinterpret_cast<__nv_bfloat162*>(dh)[t] = __floats2bfloat162_rn(v.x, v.y);
}

// ---------------------------------------------------------------------------
// Per-row stats (proven-passing version)
// ---------------------------------------------------------------------------
__global__ void k_rowstats(const float* __restrict__ X, const float* __restrict__ Y,
                           const long long* __restrict__ ids, const float* __restrict__ q) {
    __shared__ int   s_cnt[256];
    __shared__ float s_pos[256];
    const int i = blockIdx.x;
    const int t = threadIdx.x;
    const long long myid = ids[i];
    int cnt = 0;
    #pragma unroll 4
    for (int j = t; j < BATCH; j += 256) cnt += (ids[j] == myid) ? 1 : 0;
    float p = X[(size_t)i * DIM + t] * Y[(size_t)i * DIM + t];
    s_cnt[t] = cnt; s_pos[t] = p;
    __syncthreads();
    for (int s = 128; s > 0; s >>= 1) {
        if (t < s) { s_cnt[t] += s_cnt[t + s]; s_pos[t] += s_pos[t + s]; }
        __syncthreads();
    }
    if (t == 0) {
        const int n_miss = BATCH - s_cnt[0];
        const float qi = q[i];
        g_rowc[i] = logf((float)n_miss) - logf(1.0f - qi);
        g_colc[i] = logf(qi);
        g_pos[i]  = s_pos[0];
    }
}

// ---------------------------------------------------------------------------
// Main: WMMA bf16 GEMM (xh*yh) + fused masked-exp.
// 128x128 CTA tile, 256 threads / 8 warps (2x4), warp tile 64x32.
// 3-stage cp.async pipeline, 60KB dynamic smem, 2 CTAs per SM.
// ---------------------------------------------------------------------------
__global__ __launch_bounds__(256, 2)
void k_main(const long long* __restrict__ ids) {
    extern __shared__ __align__(128) __nv_bfloat16 stages[];   // NSTAGE * STAGE_ELEMS
    __shared__ float part[128 * 4];
    __shared__ float s_rc[128];
    __shared__ float s_cq[128];
    __shared__ int   s_rid[128];
    __shared__ int   s_cid[128];

    const int tid  = threadIdx.x;
    const int wid  = tid >> 5;
    const int lane = tid & 31;
    const int wm   = wid >> 2;          // 0..1 : 64-row band
    const int wn   = wid & 3;           // 0..3 : 32-col band
    const int rowBase = blockIdx.y * TM;
    const int colBase = blockIdx.x * TN;

    if (tid < 128) {
        s_rc[tid]  = g_rowc[rowBase + tid];
        s_rid[tid] = (int)ids[rowBase + tid];
        s_cq[tid]  = g_colc[colBase + tid];
        s_cid[tid] = (int)ids[colBase + tid];
    }

    wmma::fragment<wmma::accumulator, 16, 16, 16, float> acc[4][2];
    #pragma unroll
    for (int i = 0; i < 4; i++)
        #pragma unroll
        for (int j = 0; j < 2; j++) wmma::fill_fragment(acc[i][j], 0.0f);

    const int rr = tid >> 2;                 // 0..63
    const int sg = tid & 3;                  // 8-elem (16B) segment

    auto issue_chunk = [&](int chunk, int st) {
        __nv_bfloat16* sX  = stages + st * STAGE_ELEMS;
        __nv_bfloat16* sYh = sX + XT_ELEMS;
        const int kbase = chunk * KCHUNK + sg * 8;
        __pipeline_memcpy_async(sX + rr * LDE + sg * 8,
            g_Xh + (size_t)(rowBase + rr) * DIM + kbase, 16);
        __pipeline_memcpy_async(sX + (64 + rr) * LDE + sg * 8,
            g_Xh + (size_t)(rowBase + 64 + rr) * DIM + kbase, 16);
        __pipeline_memcpy_async(sYh + rr * LDE + sg * 8,
            g_Yh + (size_t)(colBase + rr) * DIM + kbase, 16);
        __pipeline_memcpy_async(sYh + (64 + rr) * LDE + sg * 8,
            g_Yh + (size_t)(colBase + 64 + rr) * DIM + kbase, 16);
        __pipeline_commit();
    };

    issue_chunk(0, 0);
    issue_chunk(1, 1);
    issue_chunk(2, 2);

    for (int c = 0; c < NCHUNK; c++) {
        const int remain = NCHUNK - 1 - c;
        if (remain >= 2)      __pipeline_wait_prior(2);
        else if (remain == 1) __pipeline_wait_prior(1);
        else                  __pipeline_wait_prior(0);
        __syncthreads();

        const int st = c % NSTAGE;
        __nv_bfloat16* sX  = stages + st * STAGE_ELEMS;
        __nv_bfloat16* sYh = sX + XT_ELEMS;

        #pragma unroll
        for (int ks = 0; ks < 2; ks++) {
            wmma::fragment<wmma::matrix_b, 16, 16, 16, __nv_bfloat16, wmma::col_major> bH[2];
            #pragma unroll
            for (int j = 0; j < 2; j++)
                wmma::load_matrix_sync(bH[j], sYh + (wn * 32 + j * 16) * LDE + ks * 16, LDE);
            #pragma unroll
            for (int i = 0; i < 4; i++) {
                wmma::fragment<wmma::matrix_a, 16, 16, 16, __nv_bfloat16, wmma::row_major> aH;
                wmma::load_matrix_sync(aH, sX + (wm * 64 + i * 16) * LDE + ks * 16, LDE);
                #pragma unroll
                for (int j = 0; j < 2; j++)
                    wmma::mma_sync(acc[i][j], aH, bH[j], acc[i][j]);
            }
        }
        __syncthreads();                       // all warps done reading stage st
        if (c + 3 < NCHUNK) issue_chunk(c + 3, st);
    }

    // ---- epilogue: per-warp 16x40 fp32 slab (reuses stage smem), masked exp ----
    float* slab = reinterpret_cast<float*>(stages) + wid * 640;   // 16 rows x ld 40
    const int erow = lane >> 1;          // 0..15
    const int eh   = lane & 1;           // half-row: cols eh*16 .. +15

    #pragma unroll
    for (int i = 0; i < 4; i++) {
        wmma::store_matrix_sync(slab,      acc[i][0], LDE, wmma::mem_row_major);
        wmma::store_matrix_sync(slab + 16, acc[i][1], LDE, wmma::mem_row_major);
        __syncwarp();
        const int lrow = wm * 64 + i * 16 + erow;
        const int idr = s_rid[lrow];
        const float rc = s_rc[lrow];
        float s = 0.0f;
        #pragma unroll
        for (int c4 = 0; c4 < 4; c4++) {
            const int cc = (c4 + erow) & 3;
            const float4 v = *reinterpret_cast<const float4*>(
                slab + erow * LDE + eh * 16 + cc * 4);
            const int cb = wn * 32 + eh * 16 + cc * 4;
            const float vv[4] = {v.x, v.y, v.z, v.w};
            #pragma unroll
            for (int e = 0; e < 4; e++) {
                const int col = cb + e;
                if (s_cid[col] != idr)
                    s += __expf(vv[e] - rc - s_cq[col]);
            }
        }
        s += __shfl_xor_sync(0xFFFFFFFFu, s, 1);
        if (eh == 0) part[lrow * 4 + wn] = s;
        __syncwarp();
    }
    __syncthreads();
    if (tid < 128)
        g_partial[(size_t)blockIdx.x * BATCH + rowBase + tid] =
            part[tid * 4] + part[tid * 4 + 1] + part[tid * 4 + 2] + part[tid * 4 + 3];
}

// ---------------------------------------------------------------------------
// Per-row loss term (deterministic reduction over column blocks)
// ---------------------------------------------------------------------------
__global__ void k_rowloss() {
    const int r = blockIdx.x * 256 + threadIdx.x;
    float s = 0.0f;
    #pragma unroll 8
    for (int c = 0; c < COLB; c++) s += g_partial[(size_t)c * BATCH + r];
    const float p = g_pos[r];
    g_terms[r] = -p + logf(expf(p) + s);
}

// ---------------------------------------------------------------------------
// Mean over rows
// ---------------------------------------------------------------------------
__global__ void k_final(float* __restrict__ out) {
    __shared__ float sm[1024];
    const int t = threadIdx.x;
    float s = 0.0f;
    for (int r = t; r < BATCH; r += 1024) s += g_terms[r];
    sm[t] = s;
    __syncthreads();
    for (int st = 512; st > 0; st >>= 1) {
        if (t < st) sm[t] += sm[t + st];
        __syncthreads();
    }
    if (t == 0) out[0] = sm[0] / (float)BATCH;
}

// ---------------------------------------------------------------------------
extern "C" void kernel_launch(void* const* d_in, const int* in_sizes, int n_in,
                              void* d_out, int out_size) {
    const float*     X   = (const float*)d_in[0];
    const float*     Y   = (const float*)d_in[1];
    const long long* ids = (const long long*)d_in[2];
    const float*     q   = (const float*)d_in[3];

    __nv_bfloat16 *xh, *yh;
    cudaGetSymbolAddress((void**)&xh, g_Xh);
    cudaGetSymbolAddress((void**)&yh, g_Yh);

    cudaFuncSetAttribute(k_main, cudaFuncAttributeMaxDynamicSharedMemorySize, SMEM_DYN);

    const int np = BATCH * DIM / 2;
    k_splitX<<<(np + 255) / 256, 256>>>(X, xh);
    k_splitX<<<(np + 255) / 256, 256>>>(Y, yh);
    k_rowstats<<<BATCH, 256>>>(X, Y, ids, q);
    dim3 grid(COLB, ROWB);
    k_main<<<grid, 256, SMEM_DYN>>>(ids);
    k_rowloss<<<BATCH / 256, 256>>>();
    k_final<<<1, 1024>>>((float*)d_out);
}